// round 10
// baseline (speedup 1.0000x reference)
#include <cuda_runtime.h>
#include <cstdint>

// x: (32,1,64,8000) fp32, a:(64,), w:(64,)
// y[b,f,t] = | x[t] - Cw * S_t |,  S_t = sum_{d=1}^{498} a^{d-1} x_edge[t-d]
// Cw = w*(1-a)/(1-a^498), edge pad x[j<0] -> x[0]
//
// One block per half-row (4000 samples + 500 halo). TMA load, LSUB=20
// chunked warm-up, vectorized B-phase, DIRECT STG.128 stores (no ys buffer).
#define T_LEN   8000
#define HALF_T  4000
#define HALO    500
#define XS_LEN  4500
#define WIN     498
#define LSUB    20
#define NSUB    200         // workers
#define NG      224         // chunk sums (NSUB + 24)
#define BLOCK   256
// float offsets in dynamic smem
#define OFF_XS   0
#define OFF_SG   4500
#define OFF_SHD  4724
#define OFF_MBAR 4948       // byte 19792: 16B-aligned
#define SMEM_BYTES (4948 * 4 + 16)

__device__ __forceinline__ float ipowf(float base, int e) {
    float p = 1.0f;
    while (e) { if (e & 1) p *= base; base *= base; e >>= 1; }
    return p;
}

__device__ __forceinline__ void mbar_wait0(uint32_t mbar) {
    uint32_t done;
    asm volatile(
        "{\n\t.reg .pred p;\n\t"
        "mbarrier.try_wait.parity.shared.b64 p, [%1], 0;\n\t"
        "selp.b32 %0, 1, 0, p;\n\t}"
        : "=r"(done) : "r"(mbar) : "memory");
    while (!done) {
        asm volatile(
            "{\n\t.reg .pred p;\n\t"
            "mbarrier.try_wait.parity.shared.b64 p, [%1], 0, 0x989680;\n\t"
            "selp.b32 %0, 1, 0, p;\n\t}"
            : "=r"(done) : "r"(mbar) : "memory");
    }
}

__global__ __launch_bounds__(BLOCK, 5)
void willmore_kernel(const float* __restrict__ x,
                     const float* __restrict__ a,
                     const float* __restrict__ w,
                     float* __restrict__ out,
                     int F) {
    extern __shared__ float sm[];
    float*  xs  = sm + OFF_XS;
    float*  sG  = sm + OFF_SG;
    float*  sHd = sm + OFF_SHD;
    float4* xs4 = (float4*)xs;
    const uint32_t mbar = (uint32_t)__cvta_generic_to_shared(sm + OFF_MBAR);

    const int tid    = threadIdx.x;
    const int row    = blockIdx.x >> 1;
    const int half   = blockIdx.x & 1;
    const int t_base = half * HALF_T;
    const int f      = row % F;
    const float* __restrict__ xrow = x + (size_t)row * T_LEN;
    float*       __restrict__ orow = out + (size_t)row * T_LEN + t_base;

    if (tid == 0)
        asm volatile("mbarrier.init.shared.b64 [%0], 1;" :: "r"(mbar) : "memory");
    __syncthreads();

    // phase A: TMA load (+ halo splat for half 0)
    if (tid == 0) {
        const int   nbytes = (half == 0) ? HALF_T * 4 : XS_LEN * 4;
        const float* src   = (half == 0) ? xrow : (xrow + t_base - HALO);
        uint32_t dst = (uint32_t)__cvta_generic_to_shared(
                           (half == 0) ? (xs + HALO) : xs);
        asm volatile("mbarrier.arrive.expect_tx.shared.b64 _, [%0], %1;"
                     :: "r"(mbar), "r"(nbytes) : "memory");
        asm volatile(
            "cp.async.bulk.shared::cluster.global.mbarrier::complete_tx::bytes "
            "[%0], [%1], %2, [%3];"
            :: "r"(dst), "l"(src), "r"(nbytes), "r"(mbar) : "memory");
    }

    // constants overlap the DMA
    const float af = __ldg(&a[f]);
    const float wf = __ldg(&w[f]);
    const float p498 = ipowf(af, WIN);
    const float Cw = (1.0f - af) / (1.0f - p498) * wf;
    const float a18 = ipowf(af, 18);
    const float a20 = a18 * af * af;

    if (half == 0) {
        const float x0v = __ldg(&xrow[0]);
        const float4 pad4 = make_float4(x0v, x0v, x0v, x0v);
        #pragma unroll
        for (int i = tid; i < HALO / 4; i += BLOCK)
            xs4[i] = pad4;   // disjoint from DMA destination
    }
    mbar_wait0(mbar);
    __syncthreads();   // splat + DMA visible to all

    // ---- B1: chunk sums over xs[20k+2 .. 20k+21], cached window in regs ----
    // G_k = Horner(20), Hd_k = first-18 prefix
    float rr[24];
    if (tid < NG) {
        float4 r4[6];
        #pragma unroll
        for (int j = 0; j < 6; ++j)
            r4[j] = xs4[5 * tid + j];          // floats 20k .. 20k+23
        #pragma unroll
        for (int j = 0; j < 6; ++j) {
            rr[4 * j + 0] = r4[j].x; rr[4 * j + 1] = r4[j].y;
            rr[4 * j + 2] = r4[j].z; rr[4 * j + 3] = r4[j].w;
        }
        float g = 0.f;
        #pragma unroll
        for (int s = 0; s < 18; ++s)           // floats 20k+2 .. 20k+19
            g = fmaf(af, g, rr[2 + s]);
        sHd[tid] = g;
        g = fmaf(af, g, rr[20]);
        g = fmaf(af, g, rr[21]);
        sG[tid] = g;
    }
    __syncthreads();

    // ---- B2: warm-up combine + sliding recurrence, direct STG.128 out ----
    if (tid < NSUB) {
        // S = Hd_{i+24} + a^18 * Horner(sG[i..i+23], a^20), farthest first
        float T = sG[tid];
        #pragma unroll
        for (int m = 1; m <= 23; ++m)
            T = fmaf(a20, T, sG[tid + m]);
        float S = fmaf(a18, T, sHd[tid + 24]);

        const int q0 = 5 * tid;                // float4 index of chunk start
        float4* __restrict__ o4 = (float4*)orow;
        #pragma unroll
        for (int j = 0; j < 5; ++j) {
            const float4 xt = xs4[125 + q0 + j];   // xs[500 + 20i + 4j ..]
            float4 yv;
            yv.x = fabsf(fmaf(-Cw, S, xt.x));
            S = fmaf(af, S, fmaf(-p498, rr[4 * j + 2], xt.x));
            yv.y = fabsf(fmaf(-Cw, S, xt.y));
            S = fmaf(af, S, fmaf(-p498, rr[4 * j + 3], xt.y));
            yv.z = fabsf(fmaf(-Cw, S, xt.z));
            S = fmaf(af, S, fmaf(-p498, rr[4 * j + 4], xt.z));
            yv.w = fabsf(fmaf(-Cw, S, xt.w));
            S = fmaf(af, S, fmaf(-p498, rr[4 * j + 5], xt.w));
            o4[q0 + j] = yv;                   // direct global store
        }
    }
    // no trailing barrier / no TMA store tail — block retires when stores issue
}

extern "C" void kernel_launch(void* const* d_in, const int* in_sizes, int n_in,
                              void* d_out, int out_size) {
    const float* x = (const float*)d_in[0];
    const float* a = (const float*)d_in[1];
    const float* w = (const float*)d_in[2];
    float* out = (float*)d_out;

    const int F = in_sizes[1];                 // 64
    const int rows = in_sizes[0] / T_LEN;      // 2048

    cudaFuncSetAttribute(willmore_kernel,
                         cudaFuncAttributeMaxDynamicSharedMemorySize, SMEM_BYTES);
    willmore_kernel<<<rows * 2, BLOCK, SMEM_BYTES>>>(x, a, w, out, F);
}

// round 11
// speedup vs baseline: 1.0708x; 1.0708x over previous
#include <cuda_runtime.h>
#include <cstdint>

// x: (32,1,64,8000) fp32, a:(64,), w:(64,)
// y[b,f,t] = | x[t] - Cw * S_t |,  S_t = sum_{d=1}^{498} a^{d-1} x_edge[t-d]
// Cw = w*(1-a)/(1-a^498), edge pad x[j<0] -> x[0]
//
// One block per QUARTER row (2000 samples + 500 halo). TMA in/out, LSUB=20
// chunked warm-up, float4-vectorized B-phase, ys staged in smem.
#define T_LEN   8000
#define TILE_T  2000
#define HALO    500
#define XS_LEN  2500
#define WIN     498
#define LSUB    20
#define NSUB    100         // workers
#define NG      124         // chunk sums (NSUB-1 + 24 + 1)
#define BLOCK   128
// float offsets in dynamic smem
#define OFF_XS   0
#define OFF_YS   2500
#define OFF_SG   4500
#define OFF_SHD  4624
#define OFF_MBAR 4748       // byte 18992: 16B-aligned
#define SMEM_BYTES (4748 * 4 + 16)

__device__ __forceinline__ float ipowf(float base, int e) {
    float p = 1.0f;
    while (e) { if (e & 1) p *= base; base *= base; e >>= 1; }
    return p;
}

__device__ __forceinline__ void mbar_wait0(uint32_t mbar) {
    uint32_t done;
    asm volatile(
        "{\n\t.reg .pred p;\n\t"
        "mbarrier.try_wait.parity.shared.b64 p, [%1], 0;\n\t"
        "selp.b32 %0, 1, 0, p;\n\t}"
        : "=r"(done) : "r"(mbar) : "memory");
    while (!done) {
        asm volatile(
            "{\n\t.reg .pred p;\n\t"
            "mbarrier.try_wait.parity.shared.b64 p, [%1], 0, 0x989680;\n\t"
            "selp.b32 %0, 1, 0, p;\n\t}"
            : "=r"(done) : "r"(mbar) : "memory");
    }
}

__global__ __launch_bounds__(BLOCK, 10)
void willmore_kernel(const float* __restrict__ x,
                     const float* __restrict__ a,
                     const float* __restrict__ w,
                     float* __restrict__ out,
                     int F) {
    extern __shared__ float sm[];
    float*  xs  = sm + OFF_XS;
    float*  ys  = sm + OFF_YS;
    float*  sG  = sm + OFF_SG;
    float*  sHd = sm + OFF_SHD;
    float4* xs4 = (float4*)xs;
    const uint32_t mbar = (uint32_t)__cvta_generic_to_shared(sm + OFF_MBAR);

    const int tid    = threadIdx.x;
    const int row    = blockIdx.x >> 2;
    const int quar   = blockIdx.x & 3;
    const int t_base = quar * TILE_T;
    const int f      = row % F;
    const float* __restrict__ xrow = x + (size_t)row * T_LEN;
    float*       __restrict__ orow = out + (size_t)row * T_LEN + t_base;

    if (tid == 0)
        asm volatile("mbarrier.init.shared.b64 [%0], 1;" :: "r"(mbar) : "memory");
    __syncthreads();

    // phase A: TMA load (+ halo splat for the first quarter)
    if (tid == 0) {
        const int   nbytes = (quar == 0) ? TILE_T * 4 : XS_LEN * 4;
        const float* src   = (quar == 0) ? xrow : (xrow + t_base - HALO);
        uint32_t dst = (uint32_t)__cvta_generic_to_shared(
                           (quar == 0) ? (xs + HALO) : xs);
        asm volatile("mbarrier.arrive.expect_tx.shared.b64 _, [%0], %1;"
                     :: "r"(mbar), "r"(nbytes) : "memory");
        asm volatile(
            "cp.async.bulk.shared::cluster.global.mbarrier::complete_tx::bytes "
            "[%0], [%1], %2, [%3];"
            :: "r"(dst), "l"(src), "r"(nbytes), "r"(mbar) : "memory");
    }

    // constants overlap the DMA
    const float af = __ldg(&a[f]);
    const float wf = __ldg(&w[f]);
    const float p498 = ipowf(af, WIN);
    const float Cw = (1.0f - af) / (1.0f - p498) * wf;
    const float a18 = ipowf(af, 18);
    const float a20 = a18 * af * af;

    if (quar == 0) {
        const float x0v = __ldg(&xrow[0]);
        const float4 pad4 = make_float4(x0v, x0v, x0v, x0v);
        #pragma unroll
        for (int i = tid; i < HALO / 4; i += BLOCK)
            xs4[i] = pad4;   // disjoint from DMA destination
    }
    mbar_wait0(mbar);
    __syncthreads();   // splat + DMA visible to all

    // ---- B1: chunk sums over xs[20k+2 .. 20k+21], window cached in regs ----
    // G_k = Horner(20), Hd_k = first-18 prefix
    float rr[24];
    if (tid < NG) {
        float4 r4[6];
        #pragma unroll
        for (int j = 0; j < 6; ++j)
            r4[j] = xs4[5 * tid + j];          // floats 20k .. 20k+23
        #pragma unroll
        for (int j = 0; j < 6; ++j) {
            rr[4 * j + 0] = r4[j].x; rr[4 * j + 1] = r4[j].y;
            rr[4 * j + 2] = r4[j].z; rr[4 * j + 3] = r4[j].w;
        }
        float g = 0.f;
        #pragma unroll
        for (int s = 0; s < 18; ++s)           // floats 20k+2 .. 20k+19
            g = fmaf(af, g, rr[2 + s]);
        sHd[tid] = g;
        g = fmaf(af, g, rr[20]);
        g = fmaf(af, g, rr[21]);
        sG[tid] = g;
    }
    __syncthreads();

    // ---- B2: warm-up combine + sliding recurrence (vectorized) ----
    if (tid < NSUB) {
        // S = Hd_{i+24} + a^18 * Horner(sG[i..i+23], a^20), farthest first
        float T = sG[tid];
        #pragma unroll
        for (int m = 1; m <= 23; ++m)
            T = fmaf(a20, T, sG[tid + m]);
        float S = fmaf(a18, T, sHd[tid + 24]);

        const int q0 = 5 * tid;                // float4 index of chunk start
        float4* ys4 = (float4*)ys;
        #pragma unroll
        for (int j = 0; j < 5; ++j) {
            const float4 xt = xs4[125 + q0 + j];   // xs[500 + 20i + 4j ..]
            float4 yv;
            yv.x = fabsf(fmaf(-Cw, S, xt.x));
            S = fmaf(af, S, fmaf(-p498, rr[4 * j + 2], xt.x));
            yv.y = fabsf(fmaf(-Cw, S, xt.y));
            S = fmaf(af, S, fmaf(-p498, rr[4 * j + 3], xt.y));
            yv.z = fabsf(fmaf(-Cw, S, xt.z));
            S = fmaf(af, S, fmaf(-p498, rr[4 * j + 4], xt.z));
            yv.w = fabsf(fmaf(-Cw, S, xt.w));
            S = fmaf(af, S, fmaf(-p498, rr[4 * j + 5], xt.w));
            ys4[q0 + j] = yv;
        }
    }
    __syncthreads();

    // ---- phase C: contiguous TMA store; release smem when read is done ----
    if (tid == 0) {
        uint32_t src = (uint32_t)__cvta_generic_to_shared(ys);
        asm volatile("fence.proxy.async.shared::cta;" ::: "memory");
        asm volatile("cp.async.bulk.global.shared::cta.bulk_group [%0], [%1], %2;"
                     :: "l"(orow), "r"(src), "r"(TILE_T * 4) : "memory");
        asm volatile("cp.async.bulk.commit_group;" ::: "memory");
        asm volatile("cp.async.bulk.wait_group.read 0;" ::: "memory");
    }
}

extern "C" void kernel_launch(void* const* d_in, const int* in_sizes, int n_in,
                              void* d_out, int out_size) {
    const float* x = (const float*)d_in[0];
    const float* a = (const float*)d_in[1];
    const float* w = (const float*)d_in[2];
    float* out = (float*)d_out;

    const int F = in_sizes[1];                 // 64
    const int rows = in_sizes[0] / T_LEN;      // 2048

    cudaFuncSetAttribute(willmore_kernel,
                         cudaFuncAttributeMaxDynamicSharedMemorySize, SMEM_BYTES);
    willmore_kernel<<<rows * 4, BLOCK, SMEM_BYTES>>>(x, a, w, out, F);
}

// round 12
// speedup vs baseline: 1.0817x; 1.0102x over previous
#include <cuda_runtime.h>
#include <cstdint>

// x: (32,1,64,8000) fp32, a:(64,), w:(64,)
// y[b,f,t] = | x[t] - Cw * S_t |,  S_t = sum_{d=1}^{498} a^{d-1} x_edge[t-d]
// Cw = w*(1-a)/(1-a^498), edge pad x[j<0] -> x[0]
//
// One block per QUARTER row (2000 samples + 500 halo). TMA in/out, LSUB=20
// chunked warm-up, float4-streamed B-phase (low regs -> 12 blocks/SM).
#define T_LEN   8000
#define TILE_T  2000
#define HALO    500
#define XS_LEN  2500
#define WIN     498
#define LSUB    20
#define NSUB    100         // workers
#define NG      124         // chunk sums
#define BLOCK   128
// float offsets in dynamic smem
#define OFF_XS   0
#define OFF_YS   2500
#define OFF_SG   4500
#define OFF_SHD  4624
#define OFF_MBAR 4748       // byte 18992: 16B-aligned
#define SMEM_BYTES (4748 * 4 + 16)

__device__ __forceinline__ float ipowf(float base, int e) {
    float p = 1.0f;
    while (e) { if (e & 1) p *= base; base *= base; e >>= 1; }
    return p;
}

__device__ __forceinline__ void mbar_wait0(uint32_t mbar) {
    uint32_t done;
    asm volatile(
        "{\n\t.reg .pred p;\n\t"
        "mbarrier.try_wait.parity.shared.b64 p, [%1], 0;\n\t"
        "selp.b32 %0, 1, 0, p;\n\t}"
        : "=r"(done) : "r"(mbar) : "memory");
    while (!done) {
        asm volatile(
            "{\n\t.reg .pred p;\n\t"
            "mbarrier.try_wait.parity.shared.b64 p, [%1], 0, 0x989680;\n\t"
            "selp.b32 %0, 1, 0, p;\n\t}"
            : "=r"(done) : "r"(mbar) : "memory");
    }
}

__global__ __launch_bounds__(BLOCK, 12)
void willmore_kernel(const float* __restrict__ x,
                     const float* __restrict__ a,
                     const float* __restrict__ w,
                     float* __restrict__ out,
                     int F) {
    extern __shared__ float sm[];
    float*  xs  = sm + OFF_XS;
    float*  ys  = sm + OFF_YS;
    float*  sG  = sm + OFF_SG;
    float*  sHd = sm + OFF_SHD;
    float4* xs4 = (float4*)xs;
    const uint32_t mbar = (uint32_t)__cvta_generic_to_shared(sm + OFF_MBAR);

    const int tid    = threadIdx.x;
    const int row    = blockIdx.x >> 2;
    const int quar   = blockIdx.x & 3;
    const int t_base = quar * TILE_T;
    const int f      = row % F;
    const float* __restrict__ xrow = x + (size_t)row * T_LEN;
    float*       __restrict__ orow = out + (size_t)row * T_LEN + t_base;

    if (tid == 0)
        asm volatile("mbarrier.init.shared.b64 [%0], 1;" :: "r"(mbar) : "memory");
    __syncthreads();

    // phase A: TMA load (+ halo splat for the first quarter)
    if (tid == 0) {
        const int   nbytes = (quar == 0) ? TILE_T * 4 : XS_LEN * 4;
        const float* src   = (quar == 0) ? xrow : (xrow + t_base - HALO);
        uint32_t dst = (uint32_t)__cvta_generic_to_shared(
                           (quar == 0) ? (xs + HALO) : xs);
        asm volatile("mbarrier.arrive.expect_tx.shared.b64 _, [%0], %1;"
                     :: "r"(mbar), "r"(nbytes) : "memory");
        asm volatile(
            "cp.async.bulk.shared::cluster.global.mbarrier::complete_tx::bytes "
            "[%0], [%1], %2, [%3];"
            :: "r"(dst), "l"(src), "r"(nbytes), "r"(mbar) : "memory");
    }

    // constants overlap the DMA
    const float af = __ldg(&a[f]);
    const float wf = __ldg(&w[f]);
    const float p498 = ipowf(af, WIN);
    const float Cw = (1.0f - af) / (1.0f - p498) * wf;
    const float a18 = ipowf(af, 18);
    const float a20 = a18 * af * af;

    if (quar == 0) {
        const float x0v = __ldg(&xrow[0]);
        const float4 pad4 = make_float4(x0v, x0v, x0v, x0v);
        #pragma unroll
        for (int i = tid; i < HALO / 4; i += BLOCK)
            xs4[i] = pad4;   // disjoint from DMA destination
    }
    mbar_wait0(mbar);
    __syncthreads();   // splat + DMA visible to all

    // ---- B1: chunk sums over xs[20k+2 .. 20k+21], quads streamed ----
    // G_k = Horner(20), Hd_k = first-18 prefix
    if (tid < NG) {
        const int b4 = 5 * tid;
        float4 q = xs4[b4];
        float g = q.z;                         // x[20k+2]
        g = fmaf(af, g, q.w);
        q = xs4[b4 + 1];
        g = fmaf(af, g, q.x); g = fmaf(af, g, q.y);
        g = fmaf(af, g, q.z); g = fmaf(af, g, q.w);
        q = xs4[b4 + 2];
        g = fmaf(af, g, q.x); g = fmaf(af, g, q.y);
        g = fmaf(af, g, q.z); g = fmaf(af, g, q.w);
        q = xs4[b4 + 3];
        g = fmaf(af, g, q.x); g = fmaf(af, g, q.y);
        g = fmaf(af, g, q.z); g = fmaf(af, g, q.w);
        q = xs4[b4 + 4];
        g = fmaf(af, g, q.x); g = fmaf(af, g, q.y);
        g = fmaf(af, g, q.z); g = fmaf(af, g, q.w);
        sHd[tid] = g;                          // 18-term prefix
        q = xs4[b4 + 5];
        g = fmaf(af, g, q.x); g = fmaf(af, g, q.y);
        sG[tid] = g;                           // full 20-term chunk sum
    }
    __syncthreads();

    // ---- B2: warm-up combine + sliding recurrence (quads streamed) ----
    if (tid < NSUB) {
        // S = Hd_{i+24} + a^18 * Horner(sG[i..i+23], a^20), farthest first
        float T = sG[tid];
        #pragma unroll
        for (int m = 1; m <= 23; ++m)
            T = fmaf(a20, T, sG[tid + m]);
        float S = fmaf(a18, T, sHd[tid + 24]);

        const int q0 = 5 * tid;                // float4 index of chunk start
        float4* ys4 = (float4*)ys;
        float4 mA = xs4[q0];                   // own-chunk quad j
        #pragma unroll
        for (int j = 0; j < 5; ++j) {
            const float4 mB = xs4[q0 + j + 1]; // own-chunk quad j+1
            const float4 xt = xs4[125 + q0 + j];
            float4 yv;
            yv.x = fabsf(fmaf(-Cw, S, xt.x));
            S = fmaf(af, S, fmaf(-p498, mA.z, xt.x));
            yv.y = fabsf(fmaf(-Cw, S, xt.y));
            S = fmaf(af, S, fmaf(-p498, mA.w, xt.y));
            yv.z = fabsf(fmaf(-Cw, S, xt.z));
            S = fmaf(af, S, fmaf(-p498, mB.x, xt.z));
            yv.w = fabsf(fmaf(-Cw, S, xt.w));
            S = fmaf(af, S, fmaf(-p498, mB.y, xt.w));
            ys4[q0 + j] = yv;
            mA = mB;
        }
    }
    __syncthreads();

    // ---- phase C: contiguous TMA store; release smem when read is done ----
    if (tid == 0) {
        uint32_t src = (uint32_t)__cvta_generic_to_shared(ys);
        asm volatile("fence.proxy.async.shared::cta;" ::: "memory");
        asm volatile("cp.async.bulk.global.shared::cta.bulk_group [%0], [%1], %2;"
                     :: "l"(orow), "r"(src), "r"(TILE_T * 4) : "memory");
        asm volatile("cp.async.bulk.commit_group;" ::: "memory");
        asm volatile("cp.async.bulk.wait_group.read 0;" ::: "memory");
    }
}

extern "C" void kernel_launch(void* const* d_in, const int* in_sizes, int n_in,
                              void* d_out, int out_size) {
    const float* x = (const float*)d_in[0];
    const float* a = (const float*)d_in[1];
    const float* w = (const float*)d_in[2];
    float* out = (float*)d_out;

    const int F = in_sizes[1];                 // 64
    const int rows = in_sizes[0] / T_LEN;      // 2048

    cudaFuncSetAttribute(willmore_kernel,
                         cudaFuncAttributeMaxDynamicSharedMemorySize, SMEM_BYTES);
    willmore_kernel<<<rows * 4, BLOCK, SMEM_BYTES>>>(x, a, w, out, F);
}